// round 12
// baseline (speedup 1.0000x reference)
#include <cuda_runtime.h>
#include <cuda_bf16.h>
#include <cstdint>

// Problem constants (B=32, S=1024, V=64, H=4096)
#define VOCAB   64
#define HID     4096
#define UOUT    128          // 2*V
#define NBLK    128          // H-split blocks
#define HCHUNK  (HID / NBLK) // 32

// Per-token output index table: out_idx[t] = (scale_idx[t]*t + loc_idx[t]) mod 64
__device__ int    g_table[VOCAB];
// Partial logits scratch: part[t][b][uq], float4 u-quads
__device__ float4 g_part[VOCAB * NBLK * (UOUT / 4)];   // 4 MB

union F2u { unsigned long long u; float2 f; };

// Packed dual-FMA: d = a*b + d on two fp32 lanes.
__device__ __forceinline__ void ffma2(unsigned long long& d,
                                      const unsigned long long a,
                                      const unsigned long long b) {
    asm("fma.rn.f32x2 %0, %1, %2, %3;" : "=l"(d) : "l"(a), "l"(b), "l"(d));
}

__device__ __forceinline__ uint32_t smem_u32(const void* p) {
    uint32_t a;
    asm("{ .reg .u64 t; cvta.to.shared.u64 t, %1; cvt.u32.u64 %0, t; }"
        : "=r"(a) : "l"(p));
    return a;
}

// ---------------------------------------------------------------------------
// K1: partial logits — FROZEN R6 configuration (best measured: 7.2-7.4us).
// Block b owns H-chunk [b*32, b*32+32). 512 threads.
// ---------------------------------------------------------------------------
__global__ __launch_bounds__(512, 1)
void partial_kernel(const float* __restrict__ W1, const float* __restrict__ b1,
                    const float* __restrict__ W2) {
    __shared__ float4 nets2[VOCAB * (HCHUNK / 2)];   // 16 KB [t][hb] dup {n,n,n',n'}
    __shared__ float4 w2s  [HCHUNK * (UOUT / 4)];    // 16 KB [h][uq]

    const int b   = blockIdx.x;
    const int tid = threadIdx.x;
    const int h0  = b * HCHUNK;

    // --- staging: all LDGs issued up front ---
    const int jt = tid >> 3;           // token 0..63
    const int jf = tid & 7;            // float4 within h-chunk
    const float4 w1v = *reinterpret_cast<const float4*>(W1 + jt * HID + h0 + jf * 4);
    const float4 b1v = *reinterpret_cast<const float4*>(b1 + h0 + jf * 4);
    const float4* __restrict__ w2src = reinterpret_cast<const float4*>(W2 + h0 * UOUT);
    const float4 w2a = w2src[tid];
    const float4 w2b = w2src[tid + 512];

    {
        float n0 = fmaxf(w1v.x + b1v.x, 0.f);
        float n1 = fmaxf(w1v.y + b1v.y, 0.f);
        float n2 = fmaxf(w1v.z + b1v.z, 0.f);
        float n3 = fmaxf(w1v.w + b1v.w, 0.f);
        nets2[jt * 16 + jf * 2 + 0] = make_float4(n0, n0, n1, n1);
        nets2[jt * 16 + jf * 2 + 1] = make_float4(n2, n2, n3, n3);
        w2s[tid]       = w2a;
        w2s[tid + 512] = w2b;
    }
    __syncthreads();

    const int uq = tid & 31;           // u-quad 0..31
    const int t0 = (tid >> 5) * 4;     // 4 tokens per thread (16 groups)

    const ulonglong2* __restrict__ n2v = reinterpret_cast<const ulonglong2*>(nets2);
    const ulonglong2* __restrict__ w2v = reinterpret_cast<const ulonglong2*>(w2s);

    unsigned long long acc[4][2];
    #pragma unroll
    for (int t = 0; t < 4; ++t) { acc[t][0] = 0ull; acc[t][1] = 0ull; }

    #pragma unroll
    for (int hb = 0; hb < HCHUNK / 2; ++hb) {              // 2 h per step
        const ulonglong2 w0 = w2v[(2 * hb)     * 32 + uq];
        const ulonglong2 w1 = w2v[(2 * hb + 1) * 32 + uq];
        #pragma unroll
        for (int t = 0; t < 4; ++t) {
            const ulonglong2 nn = n2v[(t0 + t) * 16 + hb]; // broadcast
            ffma2(acc[t][0], nn.x, w0.x);
            ffma2(acc[t][1], nn.x, w0.y);
            ffma2(acc[t][0], nn.y, w1.x);
            ffma2(acc[t][1], nn.y, w1.y);
        }
    }

    #pragma unroll
    for (int t = 0; t < 4; ++t) {
        F2u a0, a1; a0.u = acc[t][0]; a1.u = acc[t][1];
        g_part[((t0 + t) * NBLK + b) * 32 + uq] =
            make_float4(a0.f.x, a0.f.y, a1.f.x, a1.f.y);
    }
}

// ---------------------------------------------------------------------------
// K2: reduce partials over the 128 H-blocks, add b2, argmax both halves.
// One block per token, 256 threads. (FROZEN R6.)
// ---------------------------------------------------------------------------
__global__ __launch_bounds__(256, 1)
void reduce_kernel(const float* __restrict__ b2) {
    __shared__ float red[8][UOUT];
    __shared__ float logits[UOUT];

    const int t    = blockIdx.x;
    const int tid  = threadIdx.x;
    const int warp = tid >> 5;
    const int lane = tid & 31;

    float4 acc = make_float4(0.f, 0.f, 0.f, 0.f);
    const float4* base = &g_part[(t * NBLK) * 32 + lane];
    #pragma unroll 8
    for (int b = warp * 16; b < warp * 16 + 16; ++b) {
        const float4 v = base[b * 32];
        acc.x += v.x; acc.y += v.y; acc.z += v.z; acc.w += v.w;
    }
    red[warp][lane * 4 + 0] = acc.x;
    red[warp][lane * 4 + 1] = acc.y;
    red[warp][lane * 4 + 2] = acc.z;
    red[warp][lane * 4 + 3] = acc.w;
    __syncthreads();

    if (tid < UOUT) {
        float s = b2[tid];
        #pragma unroll
        for (int w = 0; w < 8; ++w) s += red[w][tid];
        logits[tid] = s;
    }
    __syncthreads();

    if (tid == 0) {
        // jnp.argmax keeps the FIRST max -> strict '>' comparison.
        int   li = 0; float lm = logits[0];
        #pragma unroll
        for (int k = 1; k < VOCAB; ++k) if (logits[k] > lm) { lm = logits[k]; li = k; }
        int   si = 0; float sm = logits[VOCAB];
        #pragma unroll
        for (int k = 1; k < VOCAB; ++k) if (logits[VOCAB + k] > sm) { sm = logits[VOCAB + k]; si = k; }
        // loc = first half, scale = second half (jnp.split order)
        g_table[t] = (si * t + li) & (VOCAB - 1);
    }
}

// ---------------------------------------------------------------------------
// K3: TMA tile load + REDUX decode + coalesced stores.
// 512 blocks x 256 threads; block owns 1024 f4 = 16 KB = 64 rows.
// R12 fix vs R11: __syncthreads() AFTER the mbarrier wait — the try_wait spin
// is per-thread and does NOT order the table_s writes (warps 0-1) against
// reads from warps 2-7. That race caused the R11 rel_err=0.33.
// ---------------------------------------------------------------------------
#define TOTAL_F4   (32 * 1024 * 64 / 4)   // 524288
#define K3_BLOCKS  512
#define K3_F4      (TOTAL_F4 / K3_BLOCKS) // 1024 f4 per block
#define K3_BYTES   (K3_F4 * 16)           // 16384

__global__ __launch_bounds__(256)
void out_kernel(const float4* __restrict__ in, float4* __restrict__ out) {
    __shared__ alignas(128) float4 tile[K3_F4];            // 16 KB
    __shared__ int table_s[VOCAB];
    __shared__ alignas(8) unsigned long long mbar;

    const int tid  = threadIdx.x;
    const int base = blockIdx.x * K3_F4;
    const uint32_t smem_mbar = smem_u32(&mbar);
    const uint32_t smem_tile = smem_u32(tile);

    if (tid == 0) {
        asm volatile("mbarrier.init.shared.b64 [%0], %1;"
                     :: "r"(smem_mbar), "r"(1u) : "memory");
    }
    __syncthreads();

    if (tid == 0) {
        asm volatile("mbarrier.arrive.expect_tx.shared.b64 _, [%0], %1;"
                     :: "r"(smem_mbar), "r"((uint32_t)K3_BYTES) : "memory");
        asm volatile("cp.async.bulk.shared::cta.global.mbarrier::complete_tx::bytes "
                     "[%0], [%1], %2, [%3];"
                     :: "r"(smem_tile), "l"(in + base),
                        "r"((uint32_t)K3_BYTES), "r"(smem_mbar)
                     : "memory");
    }

    // overlap the TMA wait with the (independent) table load
    if (tid < VOCAB) table_s[tid] = g_table[tid];

    // wait for tile (parity 0 — barrier freshly initialized each launch)
    asm volatile(
        "{\n\t.reg .pred P1;\n\t"
        "LAB_WAIT_%=:\n\t"
        "mbarrier.try_wait.parity.acquire.cta.shared::cta.b64 P1, [%0], %1;\n\t"
        "@!P1 bra LAB_WAIT_%=;\n\t}"
        :: "r"(smem_mbar), "r"(0u) : "memory");

    // Block-wide ordering point: table_s writes AND tile visibility for all
    // warps. (THE R12 FIX.)
    __syncthreads();

    const int   q    = tid & 15;             // f4 slot within row (const per thread)
    const int   lane = tid & 31;
    const unsigned mask = (lane < 16) ? 0x0000FFFFu : 0xFFFF0000u;
    const float c0 = (float)(4 * q + 1), c1 = (float)(4 * q + 2);
    const float c2 = (float)(4 * q + 3), c3 = (float)(4 * q + 4);

    #pragma unroll
    for (int i = 0; i < K3_F4 / 256; ++i) {  // 4 iterations
        const int li = tid + i * 256;
        const float4 v = tile[li];
        // exact: entries are 0.0/1.0, one hot per row -> sum is token+1
        const int p = (int)(v.x * c0 + v.y * c1 + v.z * c2 + v.w * c3);
        const int tok = __reduce_add_sync(mask, p) - 1;
        const int oi  = table_s[tok];
        float4 o = make_float4(0.f, 0.f, 0.f, 0.f);
        if ((oi >> 2) == q) reinterpret_cast<float*>(&o)[oi & 3] = 1.0f;
        out[base + li] = o;
    }
}

// ---------------------------------------------------------------------------
extern "C" void kernel_launch(void* const* d_in, const int* in_sizes, int n_in,
                              void* d_out, int out_size) {
    const float* inputs = nullptr;
    const float* W1 = nullptr;
    const float* b1 = nullptr;
    const float* W2 = nullptr;
    const float* b2 = nullptr;

    for (int i = 0; i < n_in; ++i) {
        switch (in_sizes[i]) {
            case 32 * 1024 * 64: inputs = (const float*)d_in[i]; break; // 2097152
            case 64 * 4096:      W1     = (const float*)d_in[i]; break; // 262144
            case 4096:           b1     = (const float*)d_in[i]; break;
            case 4096 * 128:     W2     = (const float*)d_in[i]; break; // 524288
            case 128:            b2     = (const float*)d_in[i]; break;
            default: break;
        }
    }

    partial_kernel<<<NBLK, 512>>>(W1, b1, W2);
    reduce_kernel<<<VOCAB, 256>>>(b2);
    out_kernel<<<K3_BLOCKS, 256>>>(
        reinterpret_cast<const float4*>(inputs),
        reinterpret_cast<float4*>(d_out));
}

// round 13
// speedup vs baseline: 1.0962x; 1.0962x over previous
#include <cuda_runtime.h>
#include <cuda_bf16.h>
#include <cstdint>

// Problem constants (B=32, S=1024, V=64, H=4096)
#define VOCAB   64
#define HID     4096
#define UOUT    128          // 2*V
#define NBLK    128          // H-split blocks
#define HCHUNK  (HID / NBLK) // 32

// Per-token output index table: out_idx[t] = (scale_idx[t]*t + loc_idx[t]) mod 64
__device__ int    g_table[VOCAB];
// Partial logits scratch: part[t][b][uq], float4 u-quads
__device__ float4 g_part[VOCAB * NBLK * (UOUT / 4)];   // 4 MB

union F2u { unsigned long long u; float2 f; };

// Packed dual-FMA: d = a*b + d on two fp32 lanes.
__device__ __forceinline__ void ffma2(unsigned long long& d,
                                      const unsigned long long a,
                                      const unsigned long long b) {
    asm("fma.rn.f32x2 %0, %1, %2, %3;" : "=l"(d) : "l"(a), "l"(b), "l"(d));
}

// ---------------------------------------------------------------------------
// K1: partial logits — FROZEN R6 configuration (best measured: 7.2-7.4us).
// Block b owns H-chunk [b*32, b*32+32). 512 threads.
// ---------------------------------------------------------------------------
__global__ __launch_bounds__(512, 1)
void partial_kernel(const float* __restrict__ W1, const float* __restrict__ b1,
                    const float* __restrict__ W2) {
    __shared__ float4 nets2[VOCAB * (HCHUNK / 2)];   // 16 KB [t][hb] dup {n,n,n',n'}
    __shared__ float4 w2s  [HCHUNK * (UOUT / 4)];    // 16 KB [h][uq]

    const int b   = blockIdx.x;
    const int tid = threadIdx.x;
    const int h0  = b * HCHUNK;

    // --- staging: all LDGs issued up front ---
    const int jt = tid >> 3;           // token 0..63
    const int jf = tid & 7;            // float4 within h-chunk
    const float4 w1v = *reinterpret_cast<const float4*>(W1 + jt * HID + h0 + jf * 4);
    const float4 b1v = *reinterpret_cast<const float4*>(b1 + h0 + jf * 4);
    const float4* __restrict__ w2src = reinterpret_cast<const float4*>(W2 + h0 * UOUT);
    const float4 w2a = w2src[tid];
    const float4 w2b = w2src[tid + 512];

    {
        float n0 = fmaxf(w1v.x + b1v.x, 0.f);
        float n1 = fmaxf(w1v.y + b1v.y, 0.f);
        float n2 = fmaxf(w1v.z + b1v.z, 0.f);
        float n3 = fmaxf(w1v.w + b1v.w, 0.f);
        nets2[jt * 16 + jf * 2 + 0] = make_float4(n0, n0, n1, n1);
        nets2[jt * 16 + jf * 2 + 1] = make_float4(n2, n2, n3, n3);
        w2s[tid]       = w2a;
        w2s[tid + 512] = w2b;
    }
    __syncthreads();

    const int uq = tid & 31;           // u-quad 0..31
    const int t0 = (tid >> 5) * 4;     // 4 tokens per thread (16 groups)

    const ulonglong2* __restrict__ n2v = reinterpret_cast<const ulonglong2*>(nets2);
    const ulonglong2* __restrict__ w2v = reinterpret_cast<const ulonglong2*>(w2s);

    unsigned long long acc[4][2];
    #pragma unroll
    for (int t = 0; t < 4; ++t) { acc[t][0] = 0ull; acc[t][1] = 0ull; }

    #pragma unroll
    for (int hb = 0; hb < HCHUNK / 2; ++hb) {              // 2 h per step
        const ulonglong2 w0 = w2v[(2 * hb)     * 32 + uq];
        const ulonglong2 w1 = w2v[(2 * hb + 1) * 32 + uq];
        #pragma unroll
        for (int t = 0; t < 4; ++t) {
            const ulonglong2 nn = n2v[(t0 + t) * 16 + hb]; // broadcast
            ffma2(acc[t][0], nn.x, w0.x);
            ffma2(acc[t][1], nn.x, w0.y);
            ffma2(acc[t][0], nn.y, w1.x);
            ffma2(acc[t][1], nn.y, w1.y);
        }
    }

    #pragma unroll
    for (int t = 0; t < 4; ++t) {
        F2u a0, a1; a0.u = acc[t][0]; a1.u = acc[t][1];
        g_part[((t0 + t) * NBLK + b) * 32 + uq] =
            make_float4(a0.f.x, a0.f.y, a1.f.x, a1.f.y);
    }
}

// ---------------------------------------------------------------------------
// K2: reduce partials over the 128 H-blocks, add b2, argmax both halves.
// One block per token, 256 threads. (FROZEN R6.)
// ---------------------------------------------------------------------------
__global__ __launch_bounds__(256, 1)
void reduce_kernel(const float* __restrict__ b2) {
    __shared__ float red[8][UOUT];
    __shared__ float logits[UOUT];

    const int t    = blockIdx.x;
    const int tid  = threadIdx.x;
    const int warp = tid >> 5;
    const int lane = tid & 31;

    float4 acc = make_float4(0.f, 0.f, 0.f, 0.f);
    const float4* base = &g_part[(t * NBLK) * 32 + lane];
    #pragma unroll 8
    for (int b = warp * 16; b < warp * 16 + 16; ++b) {
        const float4 v = base[b * 32];
        acc.x += v.x; acc.y += v.y; acc.z += v.z; acc.w += v.w;
    }
    red[warp][lane * 4 + 0] = acc.x;
    red[warp][lane * 4 + 1] = acc.y;
    red[warp][lane * 4 + 2] = acc.z;
    red[warp][lane * 4 + 3] = acc.w;
    __syncthreads();

    if (tid < UOUT) {
        float s = b2[tid];
        #pragma unroll
        for (int w = 0; w < 8; ++w) s += red[w][tid];
        logits[tid] = s;
    }
    __syncthreads();

    if (tid == 0) {
        // jnp.argmax keeps the FIRST max -> strict '>' comparison.
        int   li = 0; float lm = logits[0];
        #pragma unroll
        for (int k = 1; k < VOCAB; ++k) if (logits[k] > lm) { lm = logits[k]; li = k; }
        int   si = 0; float sm = logits[VOCAB];
        #pragma unroll
        for (int k = 1; k < VOCAB; ++k) if (logits[VOCAB + k] > sm) { sm = logits[VOCAB + k]; si = k; }
        // loc = first half, scale = second half (jnp.split order)
        g_table[t] = (si * t + li) & (VOCAB - 1);
    }
}

// ---------------------------------------------------------------------------
// K3: LDG-direct (best-measured load path) + MLP=8 + REDUX.ADD decode
// (validated exact in R12) + smem table.
// 256 blocks x 256 threads; block owns 2048 contiguous f4 (128 rows).
// Per f4: 1 up-front LDG.128, 4-FMA dot, 1 REDUX, 1 LDS table, 1 STG.128.
// ---------------------------------------------------------------------------
#define TOTAL_F4   (32 * 1024 * 64 / 4)   // 524288
#define K3_BLOCKS  256
#define K3_F4      (TOTAL_F4 / K3_BLOCKS) // 2048 f4 per block (128 rows)

__global__ __launch_bounds__(256)
void out_kernel(const float4* __restrict__ in, float4* __restrict__ out) {
    __shared__ int table_s[VOCAB];

    const int tid  = threadIdx.x;
    const int base = blockIdx.x * K3_F4;

    // --- issue all 8 independent LDG.128 up front (deep MLP) ---
    float4 v[8];
    #pragma unroll
    for (int i = 0; i < 8; ++i) v[i] = in[base + tid + i * 256];

    // --- stage table while loads are in flight ---
    if (tid < VOCAB) table_s[tid] = g_table[tid];
    __syncthreads();

    const int q    = tid & 15;               // f4 slot within row (const: 256 % 16 == 0)
    const int lane = tid & 31;
    const unsigned mask = (lane < 16) ? 0x0000FFFFu : 0xFFFF0000u;
    const float c0 = (float)(4 * q + 1), c1 = (float)(4 * q + 2);
    const float c2 = (float)(4 * q + 3), c3 = (float)(4 * q + 4);

    #pragma unroll
    for (int i = 0; i < 8; ++i) {
        // exact one-hot arithmetic: row sum of v[j]*(index+1) == token+1
        const int p   = (int)(v[i].x * c0 + v[i].y * c1 + v[i].z * c2 + v[i].w * c3);
        const int tok = __reduce_add_sync(mask, p) - 1;
        const int oi  = table_s[tok];
        float4 o = make_float4(0.f, 0.f, 0.f, 0.f);
        if ((oi >> 2) == q) reinterpret_cast<float*>(&o)[oi & 3] = 1.0f;
        out[base + tid + i * 256] = o;
    }
}

// ---------------------------------------------------------------------------
extern "C" void kernel_launch(void* const* d_in, const int* in_sizes, int n_in,
                              void* d_out, int out_size) {
    const float* inputs = nullptr;
    const float* W1 = nullptr;
    const float* b1 = nullptr;
    const float* W2 = nullptr;
    const float* b2 = nullptr;

    for (int i = 0; i < n_in; ++i) {
        switch (in_sizes[i]) {
            case 32 * 1024 * 64: inputs = (const float*)d_in[i]; break; // 2097152
            case 64 * 4096:      W1     = (const float*)d_in[i]; break; // 262144
            case 4096:           b1     = (const float*)d_in[i]; break;
            case 4096 * 128:     W2     = (const float*)d_in[i]; break; // 524288
            case 128:            b2     = (const float*)d_in[i]; break;
            default: break;
        }
    }

    partial_kernel<<<NBLK, 512>>>(W1, b1, W2);
    reduce_kernel<<<VOCAB, 256>>>(b2);
    out_kernel<<<K3_BLOCKS, 256>>>(
        reinterpret_cast<const float4*>(inputs),
        reinterpret_cast<float4*>(d_out));
}

// round 16
// speedup vs baseline: 1.1104x; 1.0130x over previous
#include <cuda_runtime.h>
#include <cuda_bf16.h>
#include <cstdint>

// Problem constants (B=32, S=1024, V=64, H=4096)
#define VOCAB   64
#define HID     4096
#define UOUT    128          // 2*V
#define NBLK    128          // H-chunks (scratch layout axis — unchanged)
#define HCHUNK  (HID / NBLK) // 32
#define TPB     32           // tokens per block (64 / 2 halves)

// Per-token output index table: out_idx[t] = (scale_idx[t]*t + loc_idx[t]) mod 64
__device__ int    g_table[VOCAB];
// Partial logits scratch: part[t][hc][uq], float4 u-quads (layout frozen for K2)
__device__ float4 g_part[VOCAB * NBLK * (UOUT / 4)];   // 4 MB

union F2u { unsigned long long u; float2 f; };

// Packed dual-FMA: d = a*b + d on two fp32 lanes.
__device__ __forceinline__ void ffma2(unsigned long long& d,
                                      const unsigned long long a,
                                      const unsigned long long b) {
    asm("fma.rn.f32x2 %0, %1, %2, %3;" : "=l"(d) : "l"(a), "l"(b), "l"(d));
}

// ---------------------------------------------------------------------------
// K1: partial logits, phase-decoupled. Grid 256 = (128 h-chunks x 2 token
// halves), 256 threads, TWO blocks per SM with independent barriers: one
// block's staging (cold LDG + sync) overlaps the other's FFMA2 compute.
// Inner loop identical to the frozen R6 kernel (4 tokens x 4 u per thread).
// ---------------------------------------------------------------------------
__global__ __launch_bounds__(256, 2)
void partial_kernel(const float* __restrict__ W1, const float* __restrict__ b1,
                    const float* __restrict__ W2) {
    __shared__ float4 nets2[TPB * (HCHUNK / 2)];     //  8 KB [t_local][hb] dup {n,n,n',n'}
    __shared__ float4 w2s  [HCHUNK * (UOUT / 4)];    // 16 KB [h][uq]

    const int hc     = blockIdx.x >> 1;      // h-chunk 0..127
    const int half   = blockIdx.x & 1;       // token half 0..1
    const int t_base = half * TPB;
    const int tid    = threadIdx.x;
    const int h0     = hc * HCHUNK;

    // --- staging: all LDGs issued up front ---
    const int jt = tid >> 3;                 // local token 0..31 (256 jobs exactly)
    const int jf = tid & 7;                  // float4 within h-chunk
    const float4 w1v = *reinterpret_cast<const float4*>(
        W1 + (t_base + jt) * HID + h0 + jf * 4);
    const float4 b1v = *reinterpret_cast<const float4*>(b1 + h0 + jf * 4);
    const float4* __restrict__ w2src = reinterpret_cast<const float4*>(W2 + h0 * UOUT);
    float4 w2v[4];
    #pragma unroll
    for (int i = 0; i < 4; ++i) w2v[i] = w2src[tid + i * 256];

    {
        float n0 = fmaxf(w1v.x + b1v.x, 0.f);
        float n1 = fmaxf(w1v.y + b1v.y, 0.f);
        float n2 = fmaxf(w1v.z + b1v.z, 0.f);
        float n3 = fmaxf(w1v.w + b1v.w, 0.f);
        nets2[jt * 16 + jf * 2 + 0] = make_float4(n0, n0, n1, n1);
        nets2[jt * 16 + jf * 2 + 1] = make_float4(n2, n2, n3, n3);
        #pragma unroll
        for (int i = 0; i < 4; ++i) w2s[tid + i * 256] = w2v[i];
    }
    __syncthreads();

    const int uq = tid & 31;                 // u-quad 0..31
    const int t0 = (tid >> 5) * 4;           // 4 local tokens per thread (8 groups)

    const ulonglong2* __restrict__ n2v = reinterpret_cast<const ulonglong2*>(nets2);
    const ulonglong2* __restrict__ w2q = reinterpret_cast<const ulonglong2*>(w2s);

    unsigned long long acc[4][2];
    #pragma unroll
    for (int t = 0; t < 4; ++t) { acc[t][0] = 0ull; acc[t][1] = 0ull; }

    #pragma unroll
    for (int hb = 0; hb < HCHUNK / 2; ++hb) {              // 2 h per step
        const ulonglong2 w0 = w2q[(2 * hb)     * 32 + uq];
        const ulonglong2 w1 = w2q[(2 * hb + 1) * 32 + uq];
        #pragma unroll
        for (int t = 0; t < 4; ++t) {
            const ulonglong2 nn = n2v[(t0 + t) * 16 + hb]; // broadcast {n,n},{n',n'}
            ffma2(acc[t][0], nn.x, w0.x);
            ffma2(acc[t][1], nn.x, w0.y);
            ffma2(acc[t][0], nn.y, w1.x);
            ffma2(acc[t][1], nn.y, w1.y);
        }
    }

    // --- write partials: part[t][hc][uq] (layout identical to R6) ---
    #pragma unroll
    for (int t = 0; t < 4; ++t) {
        F2u a0, a1; a0.u = acc[t][0]; a1.u = acc[t][1];
        g_part[((t_base + t0 + t) * NBLK + hc) * 32 + uq] =
            make_float4(a0.f.x, a0.f.y, a1.f.x, a1.f.y);
    }
}

// ---------------------------------------------------------------------------
// K2: reduce partials over the 128 H-chunks, add b2, argmax both halves.
// One block per token, 256 threads. (FROZEN R6.)
// ---------------------------------------------------------------------------
__global__ __launch_bounds__(256, 1)
void reduce_kernel(const float* __restrict__ b2) {
    __shared__ float red[8][UOUT];
    __shared__ float logits[UOUT];

    const int t    = blockIdx.x;
    const int tid  = threadIdx.x;
    const int warp = tid >> 5;
    const int lane = tid & 31;

    float4 acc = make_float4(0.f, 0.f, 0.f, 0.f);
    const float4* base = &g_part[(t * NBLK) * 32 + lane];
    #pragma unroll 8
    for (int b = warp * 16; b < warp * 16 + 16; ++b) {
        const float4 v = base[b * 32];
        acc.x += v.x; acc.y += v.y; acc.z += v.z; acc.w += v.w;
    }
    red[warp][lane * 4 + 0] = acc.x;
    red[warp][lane * 4 + 1] = acc.y;
    red[warp][lane * 4 + 2] = acc.z;
    red[warp][lane * 4 + 3] = acc.w;
    __syncthreads();

    if (tid < UOUT) {
        float s = b2[tid];
        #pragma unroll
        for (int w = 0; w < 8; ++w) s += red[w][tid];
        logits[tid] = s;
    }
    __syncthreads();

    if (tid == 0) {
        // jnp.argmax keeps the FIRST max -> strict '>' comparison.
        int   li = 0; float lm = logits[0];
        #pragma unroll
        for (int k = 1; k < VOCAB; ++k) if (logits[k] > lm) { lm = logits[k]; li = k; }
        int   si = 0; float sm = logits[VOCAB];
        #pragma unroll
        for (int k = 1; k < VOCAB; ++k) if (logits[VOCAB + k] > sm) { sm = logits[VOCAB + k]; si = k; }
        // loc = first half, scale = second half (jnp.split order)
        g_table[t] = (si * t + li) & (VOCAB - 1);
    }
}

// ---------------------------------------------------------------------------
// K3: full-row writer, MLP=4. (FROZEN R6 — best measured tail.)
// ---------------------------------------------------------------------------
#define TOTAL_F4  (32 * 1024 * 64 / 4)  // 524288
#define SC_STRIDE (TOTAL_F4 / 4)        // 131072 (multiple of 16 -> same q per k)

__global__ __launch_bounds__(256)
void out_kernel(const float4* __restrict__ in, float4* __restrict__ out) {
    const int base = blockIdx.x * 256 + threadIdx.x;
    const int q    = base & 15;

    float4 v[4];
    #pragma unroll
    for (int k = 0; k < 4; ++k) v[k] = in[base + k * SC_STRIDE];

    #pragma unroll
    for (int k = 0; k < 4; ++k) {
        int cand = -1;
        if (v[k].x > 0.5f) cand = q * 4 + 0;
        if (v[k].y > 0.5f) cand = q * 4 + 1;
        if (v[k].z > 0.5f) cand = q * 4 + 2;
        if (v[k].w > 0.5f) cand = q * 4 + 3;
        #pragma unroll
        for (int off = 8; off; off >>= 1)
            cand = max(cand, __shfl_xor_sync(0xFFFFFFFFu, cand, off, 16));

        const int oi = g_table[cand];   // uniform broadcast load
        float4 o = make_float4(0.f, 0.f, 0.f, 0.f);
        if ((oi >> 2) == q) reinterpret_cast<float*>(&o)[oi & 3] = 1.0f;
        out[base + k * SC_STRIDE] = o;
    }
}

// ---------------------------------------------------------------------------
extern "C" void kernel_launch(void* const* d_in, const int* in_sizes, int n_in,
                              void* d_out, int out_size) {
    const float* inputs = nullptr;
    const float* W1 = nullptr;
    const float* b1 = nullptr;
    const float* W2 = nullptr;
    const float* b2 = nullptr;

    for (int i = 0; i < n_in; ++i) {
        switch (in_sizes[i]) {
            case 32 * 1024 * 64: inputs = (const float*)d_in[i]; break; // 2097152
            case 64 * 4096:      W1     = (const float*)d_in[i]; break; // 262144
            case 4096:           b1     = (const float*)d_in[i]; break;
            case 4096 * 128:     W2     = (const float*)d_in[i]; break; // 524288
            case 128:            b2     = (const float*)d_in[i]; break;
            default: break;
        }
    }

    partial_kernel<<<NBLK * 2, 256>>>(W1, b1, W2);
    reduce_kernel<<<VOCAB, 256>>>(b2);
    out_kernel<<<SC_STRIDE / 256, 256>>>(
        reinterpret_cast<const float4*>(inputs),
        reinterpret_cast<float4*>(d_out));
}